// round 6
// baseline (speedup 1.0000x reference)
#include <cuda_runtime.h>
#include <cuda_bf16.h>

#ifndef HELM_PI
#define HELM_PI 3.14159265358979323846f
#endif

// out[i] = (a^2 - 2*pi^2) * sin(pi*x0) * sin(pi*x1)
//
// Fully-coalesced variant: thread t of block b loads input float4s at
// 512b+t and 512b+256+t (each LDG.128 wavefront = 4 lines, vs 8 before),
// and stores two float2 outputs at the same indices (2 lines/wavefront).
// Each input float4 = rows {2k, 2k+1} -> output float2 at index k.
__global__ void __launch_bounds__(256) helm_kernel(
    const float4* __restrict__ in4,   // N/2 float4s (2 rows each)
    const float*  __restrict__ a,
    float2*       __restrict__ out2,  // N/2 float2s (2 outputs each)
    int nq)                            // number of input float4s = N/2
{
    size_t base = (size_t)blockIdx.x * 512;
    size_t i0 = base + threadIdx.x;
    size_t i1 = i0 + 256;

    // Two independent, fully-coalesced streaming loads
    float4 v0 = __ldcs(in4 + i0);
    float4 v1 = __ldcs(in4 + i1);

    const float pi = HELM_PI;
    float av = __ldg(a);
    float coef = fmaf(av, av, -2.0f * pi * pi);

    float2 o0, o1;
    o0.x = coef * __sinf(pi * v0.x) * __sinf(pi * v0.y);
    o0.y = coef * __sinf(pi * v0.z) * __sinf(pi * v0.w);
    o1.x = coef * __sinf(pi * v1.x) * __sinf(pi * v1.y);
    o1.y = coef * __sinf(pi * v1.z) * __sinf(pi * v1.w);

    if (i0 < (size_t)nq) __stcs(out2 + i0, o0);
    if (i1 < (size_t)nq) __stcs(out2 + i1, o1);
}

extern "C" void kernel_launch(void* const* d_in, const int* in_sizes, int n_in,
                              void* d_out, int out_size)
{
    const float* in = (const float*)d_in[0];   // [N,2] float32
    const float* a  = (const float*)d_in[1];   // [1] float32

    int nq = in_sizes[0] / 4;   // number of input float4s = N/2 (N = 2^24)

    const int threads = 256;
    int blocks = (nq + 2 * threads - 1) / (2 * threads);  // 512 float4s per block

    helm_kernel<<<blocks, threads>>>(
        (const float4*)in, a, (float2*)d_out, nq);
}

// round 7
// speedup vs baseline: 1.0533x; 1.0533x over previous
#include <cuda_runtime.h>
#include <cuda_bf16.h>

#ifndef HELM_PI
#define HELM_PI 3.14159265358979323846f
#endif

// out[i] = (a^2 - 2*pi^2) * sin(pi*x0) * sin(pi*x1)
//
// Block-strided, fully-coalesced, MLP_p1 = 4:
// thread t of block b loads input float4s at 1024b + {0,256,512,768} + t
// (every LDG.128 wavefront = 4 lines) and stores four float2 outputs at the
// same indices (2 lines/wavefront). Each input float4 = 2 rows -> 1 float2.
__global__ void __launch_bounds__(256) helm_kernel(
    const float4* __restrict__ in4,   // N/2 float4s (2 rows each)
    const float*  __restrict__ a,
    float2*       __restrict__ out2,  // N/2 float2s (2 outputs each)
    int nq)                            // number of input float4s = N/2
{
    size_t base = (size_t)blockIdx.x * 1024 + threadIdx.x;
    size_t i0 = base;
    size_t i1 = base + 256;
    size_t i2 = base + 512;
    size_t i3 = base + 768;

    // Four independent, fully-coalesced streaming loads (front-batched)
    float4 v0 = __ldcs(in4 + i0);
    float4 v1 = __ldcs(in4 + i1);
    float4 v2 = __ldcs(in4 + i2);
    float4 v3 = __ldcs(in4 + i3);

    const float pi = HELM_PI;
    float av = __ldg(a);
    float coef = fmaf(av, av, -2.0f * pi * pi);

    float2 o0, o1, o2, o3;
    o0.x = coef * __sinf(pi * v0.x) * __sinf(pi * v0.y);
    o0.y = coef * __sinf(pi * v0.z) * __sinf(pi * v0.w);
    o1.x = coef * __sinf(pi * v1.x) * __sinf(pi * v1.y);
    o1.y = coef * __sinf(pi * v1.z) * __sinf(pi * v1.w);
    o2.x = coef * __sinf(pi * v2.x) * __sinf(pi * v2.y);
    o2.y = coef * __sinf(pi * v2.z) * __sinf(pi * v2.w);
    o3.x = coef * __sinf(pi * v3.x) * __sinf(pi * v3.y);
    o3.y = coef * __sinf(pi * v3.z) * __sinf(pi * v3.w);

    if (i0 < (size_t)nq) __stcs(out2 + i0, o0);
    if (i1 < (size_t)nq) __stcs(out2 + i1, o1);
    if (i2 < (size_t)nq) __stcs(out2 + i2, o2);
    if (i3 < (size_t)nq) __stcs(out2 + i3, o3);
}

extern "C" void kernel_launch(void* const* d_in, const int* in_sizes, int n_in,
                              void* d_out, int out_size)
{
    const float* in = (const float*)d_in[0];   // [N,2] float32
    const float* a  = (const float*)d_in[1];   // [1] float32

    int nq = in_sizes[0] / 4;   // number of input float4s = N/2 (N = 2^24)

    const int threads = 256;
    int blocks = (nq + 4 * threads - 1) / (4 * threads);  // 1024 float4s per block

    helm_kernel<<<blocks, threads>>>(
        (const float4*)in, a, (float2*)d_out, nq);
}